// round 9
// baseline (speedup 1.0000x reference)
#include <cuda_runtime.h>

#define BATCH   8192
#define DICTN   64
#define NDIM    8
#define MDIM    16
#define TPB     128
#define TAYLOR_D 13     // paired with theta <= 3 scaling threshold

typedef unsigned long long u64;

// ---- f32x2 packed helpers ----
__device__ __forceinline__ u64 pack2(float lo, float hi) {
    u64 r; asm("mov.b64 %0, {%1, %2};" : "=l"(r) : "f"(lo), "f"(hi)); return r;
}
__device__ __forceinline__ void unpack2(u64 v, float& lo, float& hi) {
    asm("mov.b64 {%0, %1}, %2;" : "=f"(lo), "=f"(hi) : "l"(v));
}
__device__ __forceinline__ u64 fma2(u64 a, u64 b, u64 c) {
    u64 d; asm("fma.rn.f32x2 %0, %1, %2, %3;" : "=l"(d) : "l"(a), "l"(b), "l"(c)); return d;
}
__device__ __forceinline__ u64 mul2(u64 a, u64 b) {
    u64 d; asm("mul.rn.f32x2 %0, %1, %2;" : "=l"(d) : "l"(a), "l"(b)); return d;
}

// One thread = one (b, s). A packed column-pairwise (32 x f32x2 = 64 regs).
// expm(A)x: warp-uniform scaling to theta<=3, degree-13 Taylor, Horner form
//   v <- x + (A v)/k, k = 13..1.   apps = 2^sc (typically 2).
__global__ __launch_bounds__(TPB, 5) void transop_expm_kernel(
    const float* __restrict__ x,
    const float* __restrict__ c,
    const float* __restrict__ psi,
    float* __restrict__ out)
{
    __shared__ float psis[MDIM * 64];

    const int s = blockIdx.y;
    const int b = blockIdx.x * TPB + threadIdx.x;

    // Stage psi[:, s, :, :] (64 contiguous floats per m)
    for (int l = threadIdx.x; l < MDIM * 64; l += TPB) {
        const int m = l >> 6;
        const int e = l & 63;
        psis[l] = psi[(m * DICTN + s) * 64 + e];
    }
    __syncthreads();

    // c[b, :]
    float cr[MDIM];
    {
        const float4* c4 = reinterpret_cast<const float4*>(c + (size_t)b * MDIM);
        #pragma unroll
        for (int q = 0; q < 4; q++) {
            float4 v = c4[q];
            cr[4*q+0] = v.x; cr[4*q+1] = v.y; cr[4*q+2] = v.z; cr[4*q+3] = v.w;
        }
    }

    // A-build, packed: A2[i*4+p] = (A[i][2p], A[i][2p+1])
    u64 A2[32];
    #pragma unroll
    for (int q = 0; q < 32; q++) A2[q] = 0ull;

    #pragma unroll
    for (int m = 0; m < MDIM; m++) {
        const u64 cm2 = pack2(cr[m], cr[m]);
        const ulonglong2* pm = reinterpret_cast<const ulonglong2*>(&psis[m * 64]);
        #pragma unroll
        for (int u = 0; u < 16; u++) {
            ulonglong2 pv = pm[u];          // LDS.128 warp-broadcast
            A2[2*u + 0] = fma2(cm2, pv.x, A2[2*u + 0]);
            A2[2*u + 1] = fma2(cm2, pv.y, A2[2*u + 1]);
        }
    }

    // Infinity norm
    float norm = 0.0f;
    #pragma unroll
    for (int i = 0; i < 8; i++) {
        float r = 0.0f;
        #pragma unroll
        for (int p = 0; p < 4; p++) {
            float a, bb; unpack2(A2[i*4 + p], a, bb);
            r += fabsf(a) + fabsf(bb);
        }
        norm = fmaxf(norm, r);
    }
    // Warp-uniform scaling exponent (theta <= 3)
    #pragma unroll
    for (int o = 16; o > 0; o >>= 1)
        norm = fmaxf(norm, __shfl_xor_sync(0xffffffffu, norm, o));

    int sc = 0; float nm = norm;
    while (nm > 3.0f && sc < 24) { nm *= 0.5f; sc++; }
    const float scale = __int_as_float((127 - sc) << 23);   // exact 2^-sc
    const u64 scp = pack2(scale, scale);
    #pragma unroll
    for (int q = 0; q < 32; q++) A2[q] = mul2(A2[q], scp);

    // Load x block
    float w[8];
    {
        const float4* xb = reinterpret_cast<const float4*>(x + (size_t)b * (DICTN*NDIM) + s * NDIM);
        float4 v0 = xb[0], v1 = xb[1];
        w[0]=v0.x; w[1]=v0.y; w[2]=v0.z; w[3]=v0.w;
        w[4]=v1.x; w[5]=v1.y; w[6]=v1.z; w[7]=v1.w;
    }

    const int apps = 1 << sc;
    for (int a = 0; a < apps; a++) {
        float v0_=w[0], v1_=w[1], v2_=w[2], v3_=w[3],
              v4_=w[4], v5_=w[5], v6_=w[6], v7_=w[7];

        #pragma unroll
        for (int k = TAYLOR_D; k >= 1; k--) {
            const float invk = 1.0f / (float)k;   // compile-time const -> FFMA imm form
            u64 vp0 = pack2(v0_, v1_);
            u64 vp1 = pack2(v2_, v3_);
            u64 vp2 = pack2(v4_, v5_);
            u64 vp3 = pack2(v6_, v7_);
            float vn[8];
            #pragma unroll
            for (int i = 0; i < 8; i++) {
                u64 acc = mul2(A2[i*4 + 0], vp0);
                acc = fma2(A2[i*4 + 1], vp1, acc);
                acc = fma2(A2[i*4 + 2], vp2, acc);
                acc = fma2(A2[i*4 + 3], vp3, acc);
                float lo, hi; unpack2(acc, lo, hi);
                vn[i] = fmaf(invk, lo + hi, w[i]);
            }
            v0_=vn[0]; v1_=vn[1]; v2_=vn[2]; v3_=vn[3];
            v4_=vn[4]; v5_=vn[5]; v6_=vn[6]; v7_=vn[7];
        }
        w[0]=v0_; w[1]=v1_; w[2]=v2_; w[3]=v3_;
        w[4]=v4_; w[5]=v5_; w[6]=v6_; w[7]=v7_;
    }

    // Store
    {
        float4* ob = reinterpret_cast<float4*>(out + (size_t)b * (DICTN*NDIM) + s * NDIM);
        ob[0] = make_float4(w[0], w[1], w[2], w[3]);
        ob[1] = make_float4(w[4], w[5], w[6], w[7]);
    }
}

extern "C" void kernel_launch(void* const* d_in, const int* in_sizes, int n_in,
                              void* d_out, int out_size) {
    const float* x   = (const float*)d_in[0];   // (B, 512)
    const float* c   = (const float*)d_in[1];   // (B, 16)
    const float* psi = (const float*)d_in[2];   // (16, 64, 8, 8)
    float* out = (float*)d_out;                 // (B, 512)

    dim3 grid(BATCH / TPB, DICTN);              // (64, 64)
    transop_expm_kernel<<<grid, TPB>>>(x, c, psi, out);
}

// round 10
// speedup vs baseline: 1.3418x; 1.3418x over previous
#include <cuda_runtime.h>

#define BATCH   8192
#define DICTN   64
#define NDIM    8
#define MDIM    16
#define TPB     128
#define TAYLOR_D 8      // theta <= 2 scaling; aggregate-norm error ~3e-6

typedef unsigned long long u64;

// ---- f32x2 packed helpers (A-build only; Taylor loop is scalar: on sm_103a
// FFMA2 costs 2 fma-pipe slots, so it saves issue, not pipe cycles, and we
// are pipe-cycle bound) ----
__device__ __forceinline__ u64 pack2(float lo, float hi) {
    u64 r; asm("mov.b64 %0, {%1, %2};" : "=l"(r) : "f"(lo), "f"(hi)); return r;
}
__device__ __forceinline__ void unpack2(u64 v, float& lo, float& hi) {
    asm("mov.b64 {%0, %1}, %2;" : "=f"(lo), "=f"(hi) : "l"(v));
}
__device__ __forceinline__ u64 fma2(u64 a, u64 b, u64 c) {
    u64 d; asm("fma.rn.f32x2 %0, %1, %2, %3;" : "=l"(d) : "l"(a), "l"(b), "l"(c)); return d;
}
__device__ __forceinline__ u64 mul2(u64 a, u64 b) {
    u64 d; asm("mul.rn.f32x2 %0, %1, %2;" : "=l"(d) : "l"(a), "l"(b)); return d;
}

// One thread = one (b, s).
// A[b,s] = sum_m c[b,m] * psi[m,s]; out = expm(A) @ x_block.
// Warp-uniform scaling (theta<=2, apps=2^sc), degree-8 Taylor, scalar Horner:
//   v <- x + (A v) * (1/k),  k = 8..1   (1/k as FFMA-immediate, rt=1).
__global__ __launch_bounds__(TPB, 5) void transop_expm_kernel(
    const float* __restrict__ x,
    const float* __restrict__ c,
    const float* __restrict__ psi,
    float* __restrict__ out)
{
    __shared__ float psis[MDIM * 64];

    const int s = blockIdx.y;
    const int b = blockIdx.x * TPB + threadIdx.x;

    // Stage psi[:, s, :, :] (64 contiguous floats per m)
    for (int l = threadIdx.x; l < MDIM * 64; l += TPB) {
        const int m = l >> 6;
        const int e = l & 63;
        psis[l] = psi[(m * DICTN + s) * 64 + e];
    }
    __syncthreads();

    // c[b, :]
    float cr[MDIM];
    {
        const float4* c4 = reinterpret_cast<const float4*>(c + (size_t)b * MDIM);
        #pragma unroll
        for (int q = 0; q < 4; q++) {
            float4 v = c4[q];
            cr[4*q+0] = v.x; cr[4*q+1] = v.y; cr[4*q+2] = v.z; cr[4*q+3] = v.w;
        }
    }

    // A-build, packed (half the issue slots of scalar at equal pipe cycles):
    // A2[i*4+p] = (A[i][2p], A[i][2p+1])
    u64 A2[32];
    #pragma unroll
    for (int q = 0; q < 32; q++) A2[q] = 0ull;

    #pragma unroll
    for (int m = 0; m < MDIM; m++) {
        const u64 cm2 = pack2(cr[m], cr[m]);
        const ulonglong2* pm = reinterpret_cast<const ulonglong2*>(&psis[m * 64]);
        #pragma unroll
        for (int u = 0; u < 16; u++) {
            ulonglong2 pv = pm[u];          // LDS.128 warp-broadcast
            A2[2*u + 0] = fma2(cm2, pv.x, A2[2*u + 0]);
            A2[2*u + 1] = fma2(cm2, pv.y, A2[2*u + 1]);
        }
    }

    // Infinity norm + warp-uniform scaling exponent (theta <= 2)
    float norm = 0.0f;
    #pragma unroll
    for (int i = 0; i < 8; i++) {
        float r = 0.0f;
        #pragma unroll
        for (int p = 0; p < 4; p++) {
            float a, bb; unpack2(A2[i*4 + p], a, bb);
            r += fabsf(a) + fabsf(bb);
        }
        norm = fmaxf(norm, r);
    }
    #pragma unroll
    for (int o = 16; o > 0; o >>= 1)
        norm = fmaxf(norm, __shfl_xor_sync(0xffffffffu, norm, o));

    int sc = 0; float nm = norm;
    while (nm > 2.0f && sc < 24) { nm *= 0.5f; sc++; }
    const float scale = __int_as_float((127 - sc) << 23);   // exact 2^-sc
    const u64 scp = pack2(scale, scale);
    #pragma unroll
    for (int q = 0; q < 32; q++) A2[q] = mul2(A2[q], scp);

    // Unpack A to scalars once (alu-pipe MOVs; Taylor loop stays pure fma-pipe)
    float A[64];
    #pragma unroll
    for (int i = 0; i < 8; i++) {
        #pragma unroll
        for (int p = 0; p < 4; p++) {
            unpack2(A2[i*4 + p], A[i*8 + 2*p], A[i*8 + 2*p + 1]);
        }
    }

    // Load x block
    float w[8];
    {
        const float4* xb = reinterpret_cast<const float4*>(x + (size_t)b * (DICTN*NDIM) + s * NDIM);
        float4 v0 = xb[0], v1 = xb[1];
        w[0]=v0.x; w[1]=v0.y; w[2]=v0.z; w[3]=v0.w;
        w[4]=v1.x; w[5]=v1.y; w[6]=v1.z; w[7]=v1.w;
    }

    const int apps = 1 << sc;
    for (int a = 0; a < apps; a++) {
        float v[8];
        #pragma unroll
        for (int i = 0; i < 8; i++) v[i] = w[i];

        #pragma unroll
        for (int k = TAYLOR_D; k >= 1; k--) {
            const float invk = 1.0f / (float)k;   // compile-time const -> FFMA-imm (rt=1)
            float vn[8];
            #pragma unroll
            for (int i = 0; i < 8; i++) {
                float r = A[i*8 + 0] * v[0];
                #pragma unroll
                for (int j = 1; j < 8; j++) r = fmaf(A[i*8 + j], v[j], r);
                vn[i] = fmaf(invk, r, w[i]);       // v <- x + (A v)/k
            }
            #pragma unroll
            for (int i = 0; i < 8; i++) v[i] = vn[i];
        }
        #pragma unroll
        for (int i = 0; i < 8; i++) w[i] = v[i];
    }

    // Store
    {
        float4* ob = reinterpret_cast<float4*>(out + (size_t)b * (DICTN*NDIM) + s * NDIM);
        ob[0] = make_float4(w[0], w[1], w[2], w[3]);
        ob[1] = make_float4(w[4], w[5], w[6], w[7]);
    }
}

extern "C" void kernel_launch(void* const* d_in, const int* in_sizes, int n_in,
                              void* d_out, int out_size) {
    const float* x   = (const float*)d_in[0];   // (B, 512)
    const float* c   = (const float*)d_in[1];   // (B, 16)
    const float* psi = (const float*)d_in[2];   // (16, 64, 8, 8)
    float* out = (float*)d_out;                 // (B, 512)

    dim3 grid(BATCH / TPB, DICTN);              // (64, 64)
    transop_expm_kernel<<<grid, TPB>>>(x, c, psi, out);
}